// round 12
// baseline (speedup 1.0000x reference)
#include <cuda_runtime.h>
#include <cuda_bf16.h>
#include <cstdint>

#define NB 64
#define LL 200
#define DD 300
#define DP 336           // K padded to 7*48
#define PP 16
#define EPSV 1e-12f
#define KC 48            // 3 k16 steps per chunk
#define NCH 7
#define NT_THREADS 416   // 13 warps

#define RSB 112          // row stride bytes (48 bf16 = 96B + 16B pad, conflict-free)
#define A_PLANE 23296    // 208 * 112
#define A_BUFST 46592    // hi+lo
#define B_PLANE 23296    // 208 * 112
#define B_BUFST 46592

#define SM_WSQ   0                    // 336 floats
#define SM_INV2  1344                 // 208 floats
#define SM_A     2176                 // 2 bufs x (hi|lo)
#define SM_B     (SM_A + 2*A_BUFST)   // 95360
#define SM_WRED  SM_A                 // aliased: wred used only after mainloop
#define SM_TOTAL (SM_B + 2*B_BUFST)   // 188544

__device__ float g_inv_n1[NB*LL*PP];
__device__ float g_inv_n2[NB*LL*PP];
__device__ unsigned short g_s2h[(size_t)NB*LL*DP];
__device__ unsigned short g_s2l[(size_t)NB*LL*DP];

// ---------------- PTX helpers ----------------
__device__ __forceinline__ unsigned smem_u32(const void* p) {
    unsigned a;
    asm("{ .reg .u64 t; cvta.to.shared.u64 t, %1; cvt.u32.u64 %0, t; }"
        : "=r"(a) : "l"(p));
    return a;
}

#define CP16(dst, src) \
    asm volatile("cp.async.cg.shared.global [%0], [%1], 16;" \
                 :: "r"(dst), "l"(src) : "memory")
#define CP_COMMIT() asm volatile("cp.async.commit_group;" ::: "memory")
#define CP_WAIT(n)  asm volatile("cp.async.wait_group %0;" :: "n"(n) : "memory")

#define LDSM4(r, a) \
    asm volatile("ldmatrix.sync.aligned.m8n8.x4.shared.b16 {%0,%1,%2,%3}, [%4];" \
        : "=r"((r)[0]),"=r"((r)[1]),"=r"((r)[2]),"=r"((r)[3]) : "r"(a))

#define MMA(c, a, b) \
    asm volatile("mma.sync.aligned.m16n8k16.row.col.f32.bf16.bf16.f32 " \
        "{%0,%1,%2,%3}, {%4,%5,%6,%7}, {%8,%9}, {%0,%1,%2,%3};" \
        : "+f"((c)[0]),"+f"((c)[1]),"+f"((c)[2]),"+f"((c)[3]) \
        : "r"((a)[0]),"r"((a)[1]),"r"((a)[2]),"r"((a)[3]), \
          "r"((b)[0]),"r"((b)[1]))

// ---------------------------------------------------------------------------
// norms v2: block = 64 rows; w^2 staged once; 4 rows at a time via float4.
// inv_n[row][p] = rsqrt(max(sum_d s[row,d]^2 * k[p,d]^2, eps))
// grid (NB*LL/64 = 200, 2), block 256.
// ---------------------------------------------------------------------------
__global__ void norms_kernel(const float* __restrict__ s1,
                             const float* __restrict__ s2,
                             const float* __restrict__ kern) {
    __shared__ float wsh[PP * DD];
    __shared__ float4 rsq4[DD];
    const float* src = (blockIdx.y == 0) ? s1 : s2;
    float* dst       = (blockIdx.y == 0) ? g_inv_n1 : g_inv_n2;
    int tid = threadIdx.x;
    for (int e = tid; e < PP * DD; e += 256) {
        float k = kern[e];
        wsh[e] = k * k;
    }
    int row0 = blockIdx.x * 64;
    int tx = tid & 15, ty = tid >> 4;   // tx: d stride, ty: p
    for (int g = 0; g < 16; g++) {
        int rb = row0 + g * 4;
        __syncthreads();
        for (int d = tid; d < DD; d += 256) {
            float v0 = src[(size_t)(rb + 0) * DD + d];
            float v1 = src[(size_t)(rb + 1) * DD + d];
            float v2 = src[(size_t)(rb + 2) * DD + d];
            float v3 = src[(size_t)(rb + 3) * DD + d];
            rsq4[d] = make_float4(v0*v0, v1*v1, v2*v2, v3*v3);
        }
        __syncthreads();
        float s0 = 0.f, s1v = 0.f, s2v = 0.f, s3 = 0.f;
        for (int d = tx; d < DD; d += 16) {
            float w = wsh[ty * DD + d];
            float4 r = rsq4[d];
            s0 += r.x * w; s1v += r.y * w; s2v += r.z * w; s3 += r.w * w;
        }
#pragma unroll
        for (int o = 1; o < 16; o <<= 1) {
            s0  += __shfl_xor_sync(0xffffffffu, s0, o);
            s1v += __shfl_xor_sync(0xffffffffu, s1v, o);
            s2v += __shfl_xor_sync(0xffffffffu, s2v, o);
            s3  += __shfl_xor_sync(0xffffffffu, s3, o);
        }
        if (tx == 0) {
            dst[(rb + 0) * PP + ty] = rsqrtf(fmaxf(s0, EPSV));
            dst[(rb + 1) * PP + ty] = rsqrtf(fmaxf(s1v, EPSV));
            dst[(rb + 2) * PP + ty] = rsqrtf(fmaxf(s2v, EPSV));
            dst[(rb + 3) * PP + ty] = rsqrtf(fmaxf(s3, EPSV));
        }
    }
}

// ---------------------------------------------------------------------------
// split s2 -> bf16 hi/lo, K padded to 336 with zeros
// ---------------------------------------------------------------------------
__global__ void split2_kernel(const float* __restrict__ s2) {
    size_t idx = (size_t)blockIdx.x * 256 + threadIdx.x;
    if (idx >= (size_t)NB * LL * DP) return;
    int d = (int)(idx % DP);
    size_t row = idx / DP;
    float v = (d < DD) ? s2[row * DD + d] : 0.f;
    __nv_bfloat16 h = __float2bfloat16(v);
    __nv_bfloat16 l = __float2bfloat16(v - __bfloat162float(h));
    g_s2h[idx] = *(unsigned short*)&h;
    g_s2l[idx] = *(unsigned short*)&l;
}

// ---------------------------------------------------------------------------
// stage A chunk (j-side = s2 split, 208 rows x 48): cp.async 16B
// ---------------------------------------------------------------------------
__device__ __forceinline__ void stageA(unsigned aHb, int b, int c, int tid) {
#pragma unroll
    for (int it = 0; it < 3; it++) {
        int e = tid + it * NT_THREADS;       // 0..1247 (208*6)
        int r = e / 6, sub = e - r * 6;
        int j = (r < LL) ? r : (LL - 1);
        size_t g = ((size_t)(b * LL + j)) * DP + c * KC + sub * 8;
        unsigned dst = aHb + r * RSB + sub * 16;
        CP16(dst, g_s2h + g);
        CP16(dst + A_PLANE, g_s2l + g);
    }
}

// ---------------------------------------------------------------------------
// stage B chunk (i-side = s1 * w^2, 208 rows x 48, rows>=200 & d>=300 zero)
// ---------------------------------------------------------------------------
__device__ __forceinline__ void stageB(unsigned bHb, const float* __restrict__ s1,
                                       const float* __restrict__ wsq,
                                       int b, int c, int tid) {
#pragma unroll
    for (int it = 0; it < 6; it++) {
        int e = tid + it * NT_THREADS;       // 0..2495 (208*12)
        int r = e / 12, g = e - r * 12;
        int d = c * KC + g * 4;
        float4 v = make_float4(0.f, 0.f, 0.f, 0.f);
        if (d < DD && r < LL)
            v = *(const float4*)(s1 + ((size_t)(b * LL + r)) * DD + d);
        float4 w = *(const float4*)(wsq + d);
        float a0 = v.x * w.x, a1 = v.y * w.y, a2 = v.z * w.z, a3 = v.w * w.w;
        __nv_bfloat16 h0 = __float2bfloat16(a0), h1 = __float2bfloat16(a1);
        __nv_bfloat16 h2 = __float2bfloat16(a2), h3 = __float2bfloat16(a3);
        __nv_bfloat16 l0 = __float2bfloat16(a0 - __bfloat162float(h0));
        __nv_bfloat16 l1 = __float2bfloat16(a1 - __bfloat162float(h1));
        __nv_bfloat16 l2 = __float2bfloat16(a2 - __bfloat162float(h2));
        __nv_bfloat16 l3 = __float2bfloat16(a3 - __bfloat162float(h3));
        unsigned hu0 = ((unsigned)*(unsigned short*)&h1 << 16) | *(unsigned short*)&h0;
        unsigned hu1 = ((unsigned)*(unsigned short*)&h3 << 16) | *(unsigned short*)&h2;
        unsigned lu0 = ((unsigned)*(unsigned short*)&l1 << 16) | *(unsigned short*)&l0;
        unsigned lu1 = ((unsigned)*(unsigned short*)&l3 << 16) | *(unsigned short*)&l2;
        unsigned dst = bHb + r * RSB + g * 8;
        asm volatile("st.shared.v2.b32 [%0], {%1, %2};" :: "r"(dst), "r"(hu0), "r"(hu1) : "memory");
        asm volatile("st.shared.v2.b32 [%0], {%1, %2};" :: "r"(dst + B_PLANE), "r"(lu0), "r"(lu1) : "memory");
    }
}

// ---------------------------------------------------------------------------
// Main kernel: grid (16 p, 64 b), 416 threads (13 warps).
// M = j (208, 13 m16-tiles, one per warp), N = i (208, 26 n8-tiles), K = 336.
// ---------------------------------------------------------------------------
__global__ void __launch_bounds__(NT_THREADS, 1)
mm_kernel(const float* __restrict__ s1, const float* __restrict__ s2,
          const float* __restrict__ kern, float* __restrict__ out) {
    extern __shared__ __align__(16) char smem[];
    unsigned sb = smem_u32(smem);
    float* wsq   = (float*)(smem + SM_WSQ);
    float* inv2s = (float*)(smem + SM_INV2);
    float* wred  = (float*)(smem + SM_WRED);   // aliases A tiles (dead after mainloop)

    int tid = threadIdx.x;
    int lane = tid & 31, wid = tid >> 5;
    int p = blockIdx.x, b = blockIdx.y;

    for (int e = tid; e < DP; e += NT_THREADS) {
        float k = (e < DD) ? kern[p * DD + e] : 0.f;
        wsq[e] = k * k;
    }
    for (int e = tid; e < 208; e += NT_THREADS) {
        int j = (e < LL) ? e : (LL - 1);
        inv2s[e] = g_inv_n2[(b * LL + j) * PP + p];
    }
    __syncthreads();

    float acc[26][4];
#pragma unroll
    for (int nt = 0; nt < 26; nt++)
#pragma unroll
        for (int q = 0; q < 4; q++) acc[nt][q] = 0.f;

    unsigned a_off = (unsigned)((wid * 16 + (lane & 15)) * RSB + ((lane >> 4) << 4));
    unsigned b_off = (unsigned)(((lane & 7) + ((lane >> 4) << 3)) * RSB + (((lane >> 3) & 1) << 4));

    // prologue: chunk 0 -> buf 0
    stageA(sb + SM_A, b, 0, tid);
    stageB(sb + SM_B, s1, wsq, b, 0, tid);
    CP_COMMIT();

    for (int c = 0; c < NCH; c++) {
        if (c + 1 < NCH) {
            int nb = (c + 1) & 1;
            stageA(sb + SM_A + nb * A_BUFST, b, c + 1, tid);
            stageB(sb + SM_B + nb * B_BUFST, s1, wsq, b, c + 1, tid);
            CP_COMMIT();
            CP_WAIT(1);
        } else {
            CP_WAIT(0);
        }
        __syncthreads();     // chunk c fully staged

        unsigned aH = sb + SM_A + (c & 1) * A_BUFST;
        unsigned bH = sb + SM_B + (c & 1) * B_BUFST;
        unsigned ah[4], al[4], bh[4], bl[4];
#pragma unroll
        for (int ks = 0; ks < 3; ks++) {
            unsigned aaddr = aH + a_off + ks * 32;
            LDSM4(ah, aaddr);
            LDSM4(al, aaddr + A_PLANE);
#pragma unroll
            for (int t2 = 0; t2 < 13; t2++) {
                int nt = t2 * 2;
                unsigned baddr = bH + b_off + t2 * (16 * RSB) + ks * 32;
                LDSM4(bh, baddr);
                LDSM4(bl, baddr + B_PLANE);
                MMA(acc[nt], ah, bh);
                MMA(acc[nt], ah, bl);
                MMA(acc[nt], al, bh);
                MMA(acc[nt + 1], ah, bh + 2);
                MMA(acc[nt + 1], ah, bl + 2);
                MMA(acc[nt + 1], al, bh + 2);
            }
        }
        __syncthreads();     // all warps done reading buf (c&1)
    }

    // ---- epilogue: scale by inv_n2[j], max over j ----
    // (A/B tiles are dead now; wred aliases the A region, guarded by the
    //  __syncthreads() that closed the mainloop.)
    float invA = inv2s[wid * 16 + (lane >> 2)];
    float invB = inv2s[wid * 16 + (lane >> 2) + 8];
#pragma unroll
    for (int nt = 0; nt < 26; nt++) {
        float v0 = fmaxf(acc[nt][0] * invA, acc[nt][2] * invB);
        float v1 = fmaxf(acc[nt][1] * invA, acc[nt][3] * invB);
        v0 = fmaxf(v0, __shfl_xor_sync(0xffffffffu, v0, 4));
        v0 = fmaxf(v0, __shfl_xor_sync(0xffffffffu, v0, 8));
        v0 = fmaxf(v0, __shfl_xor_sync(0xffffffffu, v0, 16));
        v1 = fmaxf(v1, __shfl_xor_sync(0xffffffffu, v1, 4));
        v1 = fmaxf(v1, __shfl_xor_sync(0xffffffffu, v1, 8));
        v1 = fmaxf(v1, __shfl_xor_sync(0xffffffffu, v1, 16));
        if (lane < 4) {
            wred[wid * 208 + nt * 8 + 2 * lane]     = v0;
            wred[wid * 208 + nt * 8 + 2 * lane + 1] = v1;
        }
    }
    __syncthreads();

    if (tid < LL) {
        float m = wred[tid];
#pragma unroll
        for (int w = 1; w < 13; w++) m = fmaxf(m, wred[w * 208 + tid]);
        out[((size_t)(b * LL + tid)) * PP + p] = m * g_inv_n1[(b * LL + tid) * PP + p];
    }
}

// ---------------------------------------------------------------------------
extern "C" void kernel_launch(void* const* d_in, const int* in_sizes, int n_in,
                              void* d_out, int out_size) {
    const float* s1   = (const float*)d_in[0];   // (64,200,300)
    const float* s2   = (const float*)d_in[1];   // (64,200,300)
    const float* kern = (const float*)d_in[2];   // (16,300)
    float* out = (float*)d_out;                  // (64,200,16)

    cudaFuncSetAttribute(mm_kernel, cudaFuncAttributeMaxDynamicSharedMemorySize,
                         SM_TOTAL);

    norms_kernel<<<dim3(NB * LL / 64, 2), 256>>>(s1, s2, kern);
    split2_kernel<<<(int)(((size_t)NB * LL * DP + 255) / 256), 256>>>(s2);
    mm_kernel<<<dim3(PP, NB), NT_THREADS, SM_TOTAL>>>(s1, s2, kern, out);
}

// round 13
// speedup vs baseline: 1.2033x; 1.2033x over previous
#include <cuda_runtime.h>
#include <cuda_bf16.h>
#include <cstdint>

#define NB 64
#define LL 200
#define DD 300
#define DP 320
#define PP 16
#define EPSV 1e-12f
#define KC 64
#define NCH 5
#define NT_THREADS 416   // 13 warps

#define RSB 144          // row stride bytes (72 bf16 = 9 x 16B, conflict-free)
#define A_PLANE 29952    // 208 * 144
#define A_BUFST 59904    // hi+lo
#define B_PLANE 14976    // 104 * 144
#define B_BUFST 29952

#define SM_WSQ   0                   // 320 floats
#define SM_INV2  1280                // 208 floats
#define SM_A     2112                // 2 bufs x (hi|lo)
#define SM_B     (SM_A + 2*A_BUFST)          // 121920
#define SM_WRED  (SM_B + 2*B_BUFST)          // 181824 (13*104 floats)
#define SM_TOTAL (SM_WRED + 13*104*4)        // 187232

__device__ float g_inv_n1[NB*LL*PP];
__device__ float g_inv_n2[NB*LL*PP];
__device__ unsigned short g_s2h[(size_t)NB*LL*DP];
__device__ unsigned short g_s2l[(size_t)NB*LL*DP];

// ---------------- PTX helpers ----------------
__device__ __forceinline__ unsigned smem_u32(const void* p) {
    unsigned a;
    asm("{ .reg .u64 t; cvta.to.shared.u64 t, %1; cvt.u32.u64 %0, t; }"
        : "=r"(a) : "l"(p));
    return a;
}

#define CP16(dst, src) \
    asm volatile("cp.async.cg.shared.global [%0], [%1], 16;" \
                 :: "r"(dst), "l"(src) : "memory")
#define CP_COMMIT() asm volatile("cp.async.commit_group;" ::: "memory")
#define CP_WAIT(n)  asm volatile("cp.async.wait_group %0;" :: "n"(n) : "memory")

#define LDSM4(r, a) \
    asm volatile("ldmatrix.sync.aligned.m8n8.x4.shared.b16 {%0,%1,%2,%3}, [%4];" \
        : "=r"((r)[0]),"=r"((r)[1]),"=r"((r)[2]),"=r"((r)[3]) : "r"(a))
#define LDSM2(r, a) \
    asm volatile("ldmatrix.sync.aligned.m8n8.x2.shared.b16 {%0,%1}, [%2];" \
        : "=r"((r)[0]),"=r"((r)[1]) : "r"(a))

#define MMA(c, a, b) \
    asm volatile("mma.sync.aligned.m16n8k16.row.col.f32.bf16.bf16.f32 " \
        "{%0,%1,%2,%3}, {%4,%5,%6,%7}, {%8,%9}, {%0,%1,%2,%3};" \
        : "+f"((c)[0]),"+f"((c)[1]),"+f"((c)[2]),"+f"((c)[3]) \
        : "r"((a)[0]),"r"((a)[1]),"r"((a)[2]),"r"((a)[3]), \
          "r"((b)[0]),"r"((b)[1]))

// packed split: (f0,f1) -> hi bf16x2 bits, lo bf16x2 bits (lo = f - float(hi))
__device__ __forceinline__ void split_pair(float f0, float f1,
                                           unsigned& hu, unsigned& lu) {
    __nv_bfloat162 h = __float22bfloat162_rn(make_float2(f0, f1));
    float2 hf = __bfloat1622float2(h);
    __nv_bfloat162 l = __float22bfloat162_rn(make_float2(f0 - hf.x, f1 - hf.y));
    hu = *(unsigned*)&h;
    lu = *(unsigned*)&l;
}

// ---------------------------------------------------------------------------
// norms v3: warp-autonomous, one initial sync only.
// block 256 (8 warps), each warp owns 8 rows; grid (NB*LL/64 = 200, 2).
// inv_n[row][p] = rsqrt(max(sum_d s[row,d]^2 * k[p,d]^2, eps))
// ---------------------------------------------------------------------------
__global__ void __launch_bounds__(256, 2)
norms_kernel(const float* __restrict__ s1, const float* __restrict__ s2,
             const float* __restrict__ kern) {
    __shared__ float wsh[PP * DD + 32];   // pad: k=9 lane>=12 reads OOB*0
    const float* src = (blockIdx.y == 0) ? s1 : s2;
    float* dst       = (blockIdx.y == 0) ? g_inv_n1 : g_inv_n2;
    int tid = threadIdx.x;
    for (int e = tid; e < PP * DD; e += 256) {
        float k = kern[e];
        wsh[e] = k * k;
    }
    if (tid < 32) wsh[PP * DD + tid] = 0.f;
    __syncthreads();

    int lane = tid & 31, warp = tid >> 5;
    int row0 = blockIdx.x * 64 + warp * 8;

    // load squares for 8 rows, strided by lane
    float sq[8][10];
#pragma unroll
    for (int r = 0; r < 8; r++) {
        const float* srow = src + (size_t)(row0 + r) * DD;
#pragma unroll
        for (int k = 0; k < 10; k++) {
            int d = lane + 32 * k;
            float v = (d < DD) ? srow[d] : 0.f;
            sq[r][k] = v * v;
        }
    }

#pragma unroll
    for (int p = 0; p < PP; p++) {
        float a[8];
#pragma unroll
        for (int r = 0; r < 8; r++) a[r] = 0.f;
#pragma unroll
        for (int k = 0; k < 10; k++) {
            float wv = wsh[p * DD + lane + 32 * k];
#pragma unroll
            for (int r = 0; r < 8; r++) a[r] += sq[r][k] * wv;
        }
#pragma unroll
        for (int r = 0; r < 8; r++) {
            float s = a[r];
            s += __shfl_xor_sync(0xffffffffu, s, 1);
            s += __shfl_xor_sync(0xffffffffu, s, 2);
            s += __shfl_xor_sync(0xffffffffu, s, 4);
            s += __shfl_xor_sync(0xffffffffu, s, 8);
            s += __shfl_xor_sync(0xffffffffu, s, 16);
            if (lane == 0)
                dst[(row0 + r) * PP + p] = rsqrtf(fmaxf(s, EPSV));
        }
    }
}

// ---------------------------------------------------------------------------
// split2 v2: s2 -> bf16 hi/lo, K padded to 320 with zeros, no div/mod in loop.
// block 320 = 4 rows x 80 float4-groups; grid NB*LL/4 = 3200.
// ---------------------------------------------------------------------------
__global__ void split2_kernel(const float* __restrict__ s2) {
    int t = threadIdx.x;
    int r = t / 80;
    int g = t - r * 80;
    int row = blockIdx.x * 4 + r;
    int d = g * 4;
    float4 v = make_float4(0.f, 0.f, 0.f, 0.f);
    if (d < DD) v = *(const float4*)(s2 + (size_t)row * DD + d);
    unsigned hu0, lu0, hu1, lu1;
    split_pair(v.x, v.y, hu0, lu0);
    split_pair(v.z, v.w, hu1, lu1);
    size_t off = (size_t)row * DP + d;
    *(uint2*)(g_s2h + off) = make_uint2(hu0, hu1);
    *(uint2*)(g_s2l + off) = make_uint2(lu0, lu1);
}

// ---------------------------------------------------------------------------
// stage A chunk (j-side = s2 split, 208 rows): cp.async 16B
// ---------------------------------------------------------------------------
__device__ __forceinline__ void stageA(unsigned aHb, int b, int c, int tid) {
#pragma unroll
    for (int it = 0; it < 4; it++) {
        int e = tid + it * NT_THREADS;       // 0..1663
        int r = e >> 3, sub = e & 7;
        int j = (r < LL) ? r : (LL - 1);
        size_t g = ((size_t)(b * LL + j)) * DP + c * KC + sub * 8;
        unsigned dst = aHb + r * RSB + sub * 16;
        CP16(dst, g_s2h + g);
        CP16(dst + A_PLANE, g_s2l + g);
    }
}

// ---------------------------------------------------------------------------
// stage B chunk (i-side = s1 * w^2, 104 rows, rows>=100 zero): slim convert
// ---------------------------------------------------------------------------
__device__ __forceinline__ void stageB(unsigned bHb, const float* __restrict__ s1,
                                       const float* __restrict__ wsq,
                                       int b, int bx, int c, int tid) {
#pragma unroll
    for (int it = 0; it < 4; it++) {
        int e = tid + it * NT_THREADS;       // 0..1663
        int r = e >> 4, g = e & 15;
        int d = c * KC + g * 4;
        float4 v = make_float4(0.f, 0.f, 0.f, 0.f);
        if (d < DD && r < 100)
            v = *(const float4*)(s1 + ((size_t)(b * LL + bx * 100 + r)) * DD + d);
        float4 w = *(const float4*)(wsq + d);
        unsigned hu0, lu0, hu1, lu1;
        split_pair(v.x * w.x, v.y * w.y, hu0, lu0);
        split_pair(v.z * w.z, v.w * w.w, hu1, lu1);
        unsigned dst = bHb + r * RSB + g * 8;
        asm volatile("st.shared.v2.b32 [%0], {%1, %2};" :: "r"(dst), "r"(hu0), "r"(hu1) : "memory");
        asm volatile("st.shared.v2.b32 [%0], {%1, %2};" :: "r"(dst + B_PLANE), "r"(lu0), "r"(lu1) : "memory");
    }
}

// ---------------------------------------------------------------------------
// Main kernel: grid (2 i-halves, 16 p, 64 b), 416 threads (13 warps).
// M = j (208, 13 m16-tiles, one per warp), N = i (104, 13 n8-tiles), K = 320.
// ---------------------------------------------------------------------------
__global__ void __launch_bounds__(NT_THREADS, 1)
mm_kernel(const float* __restrict__ s1, const float* __restrict__ s2,
          const float* __restrict__ kern, float* __restrict__ out) {
    extern __shared__ __align__(16) char smem[];
    unsigned sb = smem_u32(smem);
    float* wsq   = (float*)(smem + SM_WSQ);
    float* inv2s = (float*)(smem + SM_INV2);
    float* wred  = (float*)(smem + SM_WRED);

    int tid = threadIdx.x;
    int lane = tid & 31, wid = tid >> 5;
    int bx = blockIdx.x, p = blockIdx.y, b = blockIdx.z;

    for (int e = tid; e < DP; e += NT_THREADS) {
        float k = (e < DD) ? kern[p * DD + e] : 0.f;
        wsq[e] = k * k;
    }
    for (int e = tid; e < 208; e += NT_THREADS) {
        int j = (e < LL) ? e : (LL - 1);
        inv2s[e] = g_inv_n2[(b * LL + j) * PP + p];
    }
    __syncthreads();

    float acc[13][4];
#pragma unroll
    for (int nt = 0; nt < 13; nt++)
#pragma unroll
        for (int q = 0; q < 4; q++) acc[nt][q] = 0.f;

    unsigned a_off = (unsigned)((wid * 16 + (lane & 15)) * RSB + ((lane >> 4) << 4));
    unsigned b_off4 = (unsigned)(((lane & 7) + ((lane >> 4) << 3)) * RSB + (((lane >> 3) & 1) << 4));
    unsigned b_off2 = (unsigned)((lane & 7) * RSB + (((lane >> 3) & 1) << 4));

    // prologue: chunk 0 -> buf 0
    stageA(sb + SM_A, b, 0, tid);
    stageB(sb + SM_B, s1, wsq, b, bx, 0, tid);
    CP_COMMIT();

    for (int c = 0; c < NCH; c++) {
        if (c + 1 < NCH) {
            int nb = (c + 1) & 1;
            stageA(sb + SM_A + nb * A_BUFST, b, c + 1, tid);
            stageB(sb + SM_B + nb * B_BUFST, s1, wsq, b, bx, c + 1, tid);
            CP_COMMIT();
            CP_WAIT(1);
        } else {
            CP_WAIT(0);
        }
        __syncthreads();     // chunk c fully staged

        unsigned aH = sb + SM_A + (c & 1) * A_BUFST;
        unsigned bH = sb + SM_B + (c & 1) * B_BUFST;
        unsigned ah[4], al[4], bh[4], bl[4];
#pragma unroll
        for (int ks = 0; ks < 4; ks++) {
            unsigned aaddr = aH + a_off + ks * 32;
            LDSM4(ah, aaddr);
            LDSM4(al, aaddr + A_PLANE);
#pragma unroll
            for (int t2 = 0; t2 < 6; t2++) {
                int nt = t2 * 2;
                unsigned baddr = bH + b_off4 + nt * (8 * RSB) + ks * 32;
                LDSM4(bh, baddr);
                LDSM4(bl, baddr + B_PLANE);
                MMA(acc[nt], ah, bh);
                MMA(acc[nt], ah, bl);
                MMA(acc[nt], al, bh);
                MMA(acc[nt + 1], ah, bh + 2);
                MMA(acc[nt + 1], ah, bl + 2);
                MMA(acc[nt + 1], al, bh + 2);
            }
            unsigned baddr = bH + b_off2 + 12 * (8 * RSB) + ks * 32;
            LDSM2(bh, baddr);
            LDSM2(bl, baddr + B_PLANE);
            MMA(acc[12], ah, bh);
            MMA(acc[12], ah, bl);
            MMA(acc[12], al, bh);
        }
        __syncthreads();     // all warps done reading buf (c&1)
    }

    // ---- epilogue: scale by inv_n2[j], max over j ----
    float invA = inv2s[wid * 16 + (lane >> 2)];
    float invB = inv2s[wid * 16 + (lane >> 2) + 8];
#pragma unroll
    for (int nt = 0; nt < 13; nt++) {
        float v0 = fmaxf(acc[nt][0] * invA, acc[nt][2] * invB);
        float v1 = fmaxf(acc[nt][1] * invA, acc[nt][3] * invB);
        v0 = fmaxf(v0, __shfl_xor_sync(0xffffffffu, v0, 4));
        v0 = fmaxf(v0, __shfl_xor_sync(0xffffffffu, v0, 8));
        v0 = fmaxf(v0, __shfl_xor_sync(0xffffffffu, v0, 16));
        v1 = fmaxf(v1, __shfl_xor_sync(0xffffffffu, v1, 4));
        v1 = fmaxf(v1, __shfl_xor_sync(0xffffffffu, v1, 8));
        v1 = fmaxf(v1, __shfl_xor_sync(0xffffffffu, v1, 16));
        if (lane < 4) {
            wred[wid * 104 + nt * 8 + 2 * lane]     = v0;
            wred[wid * 104 + nt * 8 + 2 * lane + 1] = v1;
        }
    }
    __syncthreads();

    if (tid < 100) {
        int n = tid;
        float m = wred[n];
#pragma unroll
        for (int w = 1; w < 13; w++) m = fmaxf(m, wred[w * 104 + n]);
        int ig = bx * 100 + n;
        out[((size_t)(b * LL + ig)) * PP + p] = m * g_inv_n1[(b * LL + ig) * PP + p];
    }
}

// ---------------------------------------------------------------------------
extern "C" void kernel_launch(void* const* d_in, const int* in_sizes, int n_in,
                              void* d_out, int out_size) {
    const float* s1   = (const float*)d_in[0];   // (64,200,300)
    const float* s2   = (const float*)d_in[1];   // (64,200,300)
    const float* kern = (const float*)d_in[2];   // (16,300)
    float* out = (float*)d_out;                  // (64,200,16)

    cudaFuncSetAttribute(mm_kernel, cudaFuncAttributeMaxDynamicSharedMemorySize,
                         SM_TOTAL);

    norms_kernel<<<dim3(NB * LL / 64, 2), 256>>>(s1, s2, kern);
    split2_kernel<<<NB * LL / 4, 320>>>(s2);
    mm_kernel<<<dim3(2, PP, NB), NT_THREADS, SM_TOTAL>>>(s1, s2, kern, out);
}

// round 15
// speedup vs baseline: 1.2100x; 1.0056x over previous
#include <cuda_runtime.h>
#include <cuda_bf16.h>
#include <cstdint>

#define NB 64
#define LL 200
#define DD 300
#define DP 320
#define PP 16
#define EPSV 1e-12f
#define KC 32            // 2 k16 steps per chunk
#define NCH 10
#define NT_THREADS 416   // 13 warps

#define RSB 80           // row stride bytes (32 bf16 = 64B + 16B pad, conflict-free)
#define A_PLANE 16640    // 208 * 80
#define A_BUFST 33280    // hi+lo
#define B_PLANE 5760     // 72 * 80
#define B_BUFST 11520
#define NTI 72           // i rows per CTA

#define SM_WSQ   0                    // 320 floats
#define SM_INV2  1280                 // 208 floats
#define SM_A     2112                 // 2 bufs x (hi|lo)
#define SM_B     (SM_A + 2*A_BUFST)   // 68672
#define SM_WRED  (SM_B + 2*B_BUFST)   // 91712 (13*72 floats)
#define SM_TOTAL (SM_WRED + 13*NTI*4) // 95456  -> 2 CTAs/SM

__device__ float g_inv_n1[NB*LL*PP];
__device__ float g_inv_n2[NB*LL*PP];
__device__ unsigned short g_s2h[(size_t)NB*LL*DP];
__device__ unsigned short g_s2l[(size_t)NB*LL*DP];

// ---------------- PTX helpers ----------------
__device__ __forceinline__ unsigned smem_u32(const void* p) {
    unsigned a;
    asm("{ .reg .u64 t; cvta.to.shared.u64 t, %1; cvt.u32.u64 %0, t; }"
        : "=r"(a) : "l"(p));
    return a;
}

#define CP16(dst, src) \
    asm volatile("cp.async.cg.shared.global [%0], [%1], 16;" \
                 :: "r"(dst), "l"(src) : "memory")
#define CP_COMMIT() asm volatile("cp.async.commit_group;" ::: "memory")
#define CP_WAIT(n)  asm volatile("cp.async.wait_group %0;" :: "n"(n) : "memory")

#define LDSM4(r, a) \
    asm volatile("ldmatrix.sync.aligned.m8n8.x4.shared.b16 {%0,%1,%2,%3}, [%4];" \
        : "=r"((r)[0]),"=r"((r)[1]),"=r"((r)[2]),"=r"((r)[3]) : "r"(a))
#define LDSM2(r, a) \
    asm volatile("ldmatrix.sync.aligned.m8n8.x2.shared.b16 {%0,%1}, [%2];" \
        : "=r"((r)[0]),"=r"((r)[1]) : "r"(a))

#define MMA(c, a, b) \
    asm volatile("mma.sync.aligned.m16n8k16.row.col.f32.bf16.bf16.f32 " \
        "{%0,%1,%2,%3}, {%4,%5,%6,%7}, {%8,%9}, {%0,%1,%2,%3};" \
        : "+f"((c)[0]),"+f"((c)[1]),"+f"((c)[2]),"+f"((c)[3]) \
        : "r"((a)[0]),"r"((a)[1]),"r"((a)[2]),"r"((a)[3]), \
          "r"((b)[0]),"r"((b)[1]))

// packed split: (f0,f1) -> hi bf16x2 bits, lo bf16x2 bits (lo = f - float(hi))
__device__ __forceinline__ void split_pair(float f0, float f1,
                                           unsigned& hu, unsigned& lu) {
    __nv_bfloat162 h = __float22bfloat162_rn(make_float2(f0, f1));
    float2 hf = __bfloat1622float2(h);
    __nv_bfloat162 l = __float22bfloat162_rn(make_float2(f0 - hf.x, f1 - hf.y));
    hu = *(unsigned*)&h;
    lu = *(unsigned*)&l;
}

// ---------------------------------------------------------------------------
// norms v4: block 256 (8 warps), 32 rows/block, 4 rows/warp, single sync.
// inv_n[row][p] = rsqrt(max(sum_d s[row,d]^2 * k[p,d]^2, eps))
// grid (NB*LL/32 = 400, 2).
// ---------------------------------------------------------------------------
__global__ void __launch_bounds__(256)
norms_kernel(const float* __restrict__ s1, const float* __restrict__ s2,
             const float* __restrict__ kern) {
    __shared__ float wsh[PP * DD + 32];   // zero tail: d>=300 lanes read 0
    const float* src = (blockIdx.y == 0) ? s1 : s2;
    float* dst       = (blockIdx.y == 0) ? g_inv_n1 : g_inv_n2;
    int tid = threadIdx.x;
    for (int e = tid; e < PP * DD; e += 256) {
        float k = kern[e];
        wsh[e] = k * k;
    }
    if (tid < 32) wsh[PP * DD + tid] = 0.f;
    __syncthreads();

    int lane = tid & 31, warp = tid >> 5;
    int row0 = blockIdx.x * 32 + warp * 4;

    float sq[4][10];
#pragma unroll
    for (int r = 0; r < 4; r++) {
        const float* srow = src + (size_t)(row0 + r) * DD;
#pragma unroll
        for (int k = 0; k < 10; k++) {
            int d = lane + 32 * k;
            float v = (d < DD) ? srow[d] : 0.f;
            sq[r][k] = v * v;
        }
    }

#pragma unroll
    for (int p = 0; p < PP; p++) {
        float a[4];
#pragma unroll
        for (int r = 0; r < 4; r++) a[r] = 0.f;
#pragma unroll
        for (int k = 0; k < 10; k++) {
            float wv = wsh[p * DD + lane + 32 * k];
#pragma unroll
            for (int r = 0; r < 4; r++) a[r] += sq[r][k] * wv;
        }
#pragma unroll
        for (int r = 0; r < 4; r++) {
            float s = a[r];
            s += __shfl_xor_sync(0xffffffffu, s, 1);
            s += __shfl_xor_sync(0xffffffffu, s, 2);
            s += __shfl_xor_sync(0xffffffffu, s, 4);
            s += __shfl_xor_sync(0xffffffffu, s, 8);
            s += __shfl_xor_sync(0xffffffffu, s, 16);
            if (lane == 0)
                dst[(row0 + r) * PP + p] = rsqrtf(fmaxf(s, EPSV));
        }
    }
}

// ---------------------------------------------------------------------------
// split2: s2 -> bf16 hi/lo, K padded to 320 with zeros, no div/mod.
// block 320 = 4 rows x 80 float4-groups; grid NB*LL/4 = 3200.
// ---------------------------------------------------------------------------
__global__ void split2_kernel(const float* __restrict__ s2) {
    int t = threadIdx.x;
    int r = t / 80;
    int g = t - r * 80;
    int row = blockIdx.x * 4 + r;
    int d = g * 4;
    float4 v = make_float4(0.f, 0.f, 0.f, 0.f);
    if (d < DD) v = *(const float4*)(s2 + (size_t)row * DD + d);
    unsigned hu0, lu0, hu1, lu1;
    split_pair(v.x, v.y, hu0, lu0);
    split_pair(v.z, v.w, hu1, lu1);
    size_t off = (size_t)row * DP + d;
    *(uint2*)(g_s2h + off) = make_uint2(hu0, hu1);
    *(uint2*)(g_s2l + off) = make_uint2(lu0, lu1);
}

// ---------------------------------------------------------------------------
// stage A chunk (j-side = s2 split, 208 rows x 32): cp.async 16B, 2 its
// ---------------------------------------------------------------------------
__device__ __forceinline__ void stageA(unsigned aHb, int b, int c, int tid) {
#pragma unroll
    for (int it = 0; it < 2; it++) {
        int e = tid + it * NT_THREADS;       // 0..831 (208*4)
        int r = e >> 2, sub = e & 3;
        int j = (r < LL) ? r : (LL - 1);
        size_t g = ((size_t)(b * LL + j)) * DP + c * KC + sub * 8;
        unsigned dst = aHb + r * RSB + sub * 16;
        CP16(dst, g_s2h + g);
        CP16(dst + A_PLANE, g_s2l + g);
    }
}

// ---------------------------------------------------------------------------
// stage B chunk (i-side = s1 * w^2, 72 rows x 32): convert in-CTA, 2 its
// ---------------------------------------------------------------------------
__device__ __forceinline__ void stageB(unsigned bHb, const float* __restrict__ s1,
                                       const float* __restrict__ wsq,
                                       int b, int bx, int c, int tid) {
#pragma unroll
    for (int it = 0; it < 2; it++) {
        int e = tid + it * NT_THREADS;       // need 0..575 (72*8)
        if (e < NTI * 8) {
            int r = e >> 3, g = e & 7;
            int d = c * KC + g * 4;
            int ig = bx * NTI + r;
            float4 v = make_float4(0.f, 0.f, 0.f, 0.f);
            if (d < DD && ig < LL)
                v = *(const float4*)(s1 + ((size_t)(b * LL + ig)) * DD + d);
            float4 w = *(const float4*)(wsq + d);
            unsigned hu0, lu0, hu1, lu1;
            split_pair(v.x * w.x, v.y * w.y, hu0, lu0);
            split_pair(v.z * w.z, v.w * w.w, hu1, lu1);
            unsigned dst = bHb + r * RSB + g * 8;
            asm volatile("st.shared.v2.b32 [%0], {%1, %2};" :: "r"(dst), "r"(hu0), "r"(hu1) : "memory");
            asm volatile("st.shared.v2.b32 [%0], {%1, %2};" :: "r"(dst + B_PLANE), "r"(lu0), "r"(lu1) : "memory");
        }
    }
}

// ---------------------------------------------------------------------------
// Main kernel: grid (3 i-thirds, 16 p, 64 b), 416 threads (13 warps), occ 2.
// M = j (208, 13 m16-tiles, one per warp), N = i (72, 9 n8-tiles), K = 320.
// ---------------------------------------------------------------------------
__global__ void __launch_bounds__(NT_THREADS, 2)
mm_kernel(const float* __restrict__ s1, const float* __restrict__ s2,
          const float* __restrict__ kern, float* __restrict__ out) {
    extern __shared__ __align__(16) char smem[];
    unsigned sb = smem_u32(smem);
    float* wsq   = (float*)(smem + SM_WSQ);
    float* inv2s = (float*)(smem + SM_INV2);
    float* wred  = (float*)(smem + SM_WRED);

    int tid = threadIdx.x;
    int lane = tid & 31, wid = tid >> 5;
    int bx = blockIdx.x, p = blockIdx.y, b = blockIdx.z;

    for (int e = tid; e < DP; e += NT_THREADS) {
        float k = (e < DD) ? kern[p * DD + e] : 0.f;
        wsq[e] = k * k;
    }
    for (int e = tid; e < 208; e += NT_THREADS) {
        int j = (e < LL) ? e : (LL - 1);
        inv2s[e] = g_inv_n2[(b * LL + j) * PP + p];
    }
    __syncthreads();

    float acc[9][4];
#pragma unroll
    for (int nt = 0; nt < 9; nt++)
#pragma unroll
        for (int q = 0; q < 4; q++) acc[nt][q] = 0.f;

    unsigned a_off = (unsigned)((wid * 16 + (lane & 15)) * RSB + ((lane >> 4) << 4));
    unsigned b_off4 = (unsigned)(((lane & 7) + ((lane >> 4) << 3)) * RSB + (((lane >> 3) & 1) << 4));
    unsigned b_off2 = (unsigned)((lane & 7) * RSB + (((lane >> 3) & 1) << 4));

    // prologue: chunk 0 -> buf 0
    stageA(sb + SM_A, b, 0, tid);
    stageB(sb + SM_B, s1, wsq, b, bx, 0, tid);
    CP_COMMIT();

    for (int c = 0; c < NCH; c++) {
        if (c + 1 < NCH) {
            int nb = (c + 1) & 1;
            stageA(sb + SM_A + nb * A_BUFST, b, c + 1, tid);
            stageB(sb + SM_B + nb * B_BUFST, s1, wsq, b, bx, c + 1, tid);
            CP_COMMIT();
            CP_WAIT(1);
        } else {
            CP_WAIT(0);
        }
        __syncthreads();     // chunk c fully staged

        unsigned aH = sb + SM_A + (c & 1) * A_BUFST;
        unsigned bH = sb + SM_B + (c & 1) * B_BUFST;
        unsigned ah[4], al[4], bh[4], bl[4];
#pragma unroll
        for (int ks = 0; ks < 2; ks++) {
            unsigned aaddr = aH + a_off + ks * 32;
            LDSM4(ah, aaddr);
            LDSM4(al, aaddr + A_PLANE);
#pragma unroll
            for (int t2 = 0; t2 < 4; t2++) {
                int nt = t2 * 2;
                unsigned baddr = bH + b_off4 + t2 * (16 * RSB) + ks * 32;
                LDSM4(bh, baddr);
                LDSM4(bl, baddr + B_PLANE);
                MMA(acc[nt], ah, bh);
                MMA(acc[nt], ah, bl);
                MMA(acc[nt], al, bh);
                MMA(acc[nt + 1], ah, bh + 2);
                MMA(acc[nt + 1], ah, bl + 2);
                MMA(acc[nt + 1], al, bh + 2);
            }
            unsigned baddr = bH + b_off2 + 8 * (8 * RSB) + ks * 32;
            LDSM2(bh, baddr);
            LDSM2(bl, baddr + B_PLANE);
            MMA(acc[8], ah, bh);
            MMA(acc[8], ah, bl);
            MMA(acc[8], al, bh);
        }
        __syncthreads();     // all warps done reading buf (c&1)
    }

    // ---- epilogue: scale by inv_n2[j], max over j ----
    float invA = inv2s[wid * 16 + (lane >> 2)];
    float invB = inv2s[wid * 16 + (lane >> 2) + 8];
#pragma unroll
    for (int nt = 0; nt < 9; nt++) {
        float v0 = fmaxf(acc[nt][0] * invA, acc[nt][2] * invB);
        float v1 = fmaxf(acc[nt][1] * invA, acc[nt][3] * invB);
        v0 = fmaxf(v0, __shfl_xor_sync(0xffffffffu, v0, 4));
        v0 = fmaxf(v0, __shfl_xor_sync(0xffffffffu, v0, 8));
        v0 = fmaxf(v0, __shfl_xor_sync(0xffffffffu, v0, 16));
        v1 = fmaxf(v1, __shfl_xor_sync(0xffffffffu, v1, 4));
        v1 = fmaxf(v1, __shfl_xor_sync(0xffffffffu, v1, 8));
        v1 = fmaxf(v1, __shfl_xor_sync(0xffffffffu, v1, 16));
        if (lane < 4) {
            wred[wid * NTI + nt * 8 + 2 * lane]     = v0;
            wred[wid * NTI + nt * 8 + 2 * lane + 1] = v1;
        }
    }
    __syncthreads();

    if (tid < NTI) {
        int ig = bx * NTI + tid;
        if (ig < LL) {
            float m = wred[tid];
#pragma unroll
            for (int w = 1; w < 13; w++) m = fmaxf(m, wred[w * NTI + tid]);
            out[((size_t)(b * LL + ig)) * PP + p] = m * g_inv_n1[(b * LL + ig) * PP + p];
        }
    }
}

// ---------------------------------------------------------------------------
extern "C" void kernel_launch(void* const* d_in, const int* in_sizes, int n_in,
                              void* d_out, int out_size) {
    const float* s1   = (const float*)d_in[0];   // (64,200,300)
    const float* s2   = (const float*)d_in[1];   // (64,200,300)
    const float* kern = (const float*)d_in[2];   // (16,300)
    float* out = (float*)d_out;                  // (64,200,16)

    cudaFuncSetAttribute(mm_kernel, cudaFuncAttributeMaxDynamicSharedMemorySize,
                         SM_TOTAL);

    norms_kernel<<<dim3(NB * LL / 32, 2), 256>>>(s1, s2, kern);
    split2_kernel<<<NB * LL / 4, 320>>>(s2);
    mm_kernel<<<dim3(3, PP, NB), NT_THREADS, SM_TOTAL>>>(s1, s2, kern, out);
}